// round 1
// baseline (speedup 1.0000x reference)
#include <cuda_runtime.h>
#include <math.h>

#define HH 192
#define WW 192
#define HW (HH*WW)       // 36864
#define CB 128
#define BATCH 2

// ---------------- scratch (device globals; no runtime allocation) ----------------
__device__ float g_buf512[(size_t)BATCH*512*HW];  // y1 (stage A) / z1 (stage C)
__device__ float g_qkv  [(size_t)BATCH*384*HW];   // qkv
__device__ float g_gate [(size_t)BATCH*256*HW];   // gated act (stage A) / attn out (reuse)
__device__ float g_x1   [(size_t)BATCH*128*HW];   // x after conv block
__device__ float g_invr [(size_t)BATCH*HW];       // per-pixel 1/rms

__device__ __forceinline__ float gelu_f(float x) {
    return 0.5f * x * (1.0f + erff(x * 0.70710678118654752f));
}

// ---------------- per-pixel inverse RMS over 128 channels ----------------
__global__ void invrms_kernel(const float* __restrict__ x, float* __restrict__ invr) {
    int idx = blockIdx.x * blockDim.x + threadIdx.x;   // 0..B*HW-1
    int b = idx / HW, p = idx - b * HW;
    const float* xp = x + (size_t)b * CB * HW + p;
    float acc = 0.f;
    #pragma unroll 8
    for (int c = 0; c < CB; ++c) { float v = xp[(size_t)c * HW]; acc = fmaf(v, v, acc); }
    invr[idx] = rsqrtf(acc * (1.0f / CB) + 1e-6f);
}

// ---------------- unified fused SGEMM: out[o][p] = epi( sum_k W[o][k] * Aval(k,p) ) ---------
// AMODE 0: Aval = A[k][p]
// AMODE 1: Aval = s[k]*A[k][p]*invr[p] + rb[k]          (rmsnorm fused)
// AMODE 2: Aval = A[k][p] * gelu(A[k+256][p])           (gated-GELU fused, K=256)
// EPI 0:   out = acc + bias[o]
// EPI 1:   out = R[o][p] + coef*(acc + bias[o])
template<int AMODE, int EPI>
__global__ __launch_bounds__(256)
void gemm128(const float* __restrict__ W,
             const float* __restrict__ A,
             const float* __restrict__ bias,
             const float* __restrict__ s,
             const float* __restrict__ rb,
             const float* __restrict__ invr,
             const float* __restrict__ R,
             const float* __restrict__ coefp,
             float* __restrict__ out,
             int K, long strideA, long strideO)
{
    __shared__ float Ws[16][128];
    __shared__ float As[16][128];

    int b = blockIdx.z;
    int p0 = blockIdx.x * 128;
    int oBase = blockIdx.y * 128;
    A   += (size_t)b * strideA;
    out += (size_t)b * strideO;
    const float* Rb   = (EPI == 1) ? (R + (size_t)b * 128 * HW) : nullptr;
    const float* invb = (AMODE == 1) ? (invr + (size_t)b * HW) : nullptr;

    int tid = threadIdx.x;
    int wo = tid >> 1;            // 0..127  (W row within tile)
    int wc = (tid & 1) * 8;       // 0 or 8  (W col chunk)
    int ak = tid >> 4;            // 0..15   (A k row)
    int ap = (tid & 15) * 8;      // 0..120  (A pixel chunk)
    int m0 = (tid >> 4) * 8;
    int n0 = (tid & 15) * 8;

    float acc[8][8];
    #pragma unroll
    for (int i = 0; i < 8; i++)
        #pragma unroll
        for (int j = 0; j < 8; j++) acc[i][j] = 0.f;

    for (int k0 = 0; k0 < K; k0 += 16) {
        // W tile -> Ws[k][m]
        {
            const float* wp = W + (size_t)(oBase + wo) * K + (k0 + wc);
            float4 w0 = *(const float4*)wp;
            float4 w1 = *(const float4*)(wp + 4);
            Ws[wc+0][wo] = w0.x; Ws[wc+1][wo] = w0.y; Ws[wc+2][wo] = w0.z; Ws[wc+3][wo] = w0.w;
            Ws[wc+4][wo] = w1.x; Ws[wc+5][wo] = w1.y; Ws[wc+6][wo] = w1.z; Ws[wc+7][wo] = w1.w;
        }
        // A tile -> As[k][n]  (with fused transform)
        {
            const float* ag = A + (size_t)(k0 + ak) * HW + (p0 + ap);
            float4 a0 = *(const float4*)ag;
            float4 a1 = *(const float4*)(ag + 4);
            if (AMODE == 1) {
                float sc = __ldg(s + k0 + ak), bb = __ldg(rb + k0 + ak);
                float4 i0 = *(const float4*)(invb + p0 + ap);
                float4 i1 = *(const float4*)(invb + p0 + ap + 4);
                a0.x = fmaf(sc*a0.x, i0.x, bb); a0.y = fmaf(sc*a0.y, i0.y, bb);
                a0.z = fmaf(sc*a0.z, i0.z, bb); a0.w = fmaf(sc*a0.w, i0.w, bb);
                a1.x = fmaf(sc*a1.x, i1.x, bb); a1.y = fmaf(sc*a1.y, i1.y, bb);
                a1.z = fmaf(sc*a1.z, i1.z, bb); a1.w = fmaf(sc*a1.w, i1.w, bb);
            } else if (AMODE == 2) {
                const float* vg = ag + (size_t)256 * HW;
                float4 v0 = *(const float4*)vg;
                float4 v1 = *(const float4*)(vg + 4);
                a0.x *= gelu_f(v0.x); a0.y *= gelu_f(v0.y);
                a0.z *= gelu_f(v0.z); a0.w *= gelu_f(v0.w);
                a1.x *= gelu_f(v1.x); a1.y *= gelu_f(v1.y);
                a1.z *= gelu_f(v1.z); a1.w *= gelu_f(v1.w);
            }
            *(float4*)&As[ak][ap]     = a0;
            *(float4*)&As[ak][ap + 4] = a1;
        }
        __syncthreads();
        #pragma unroll
        for (int kk = 0; kk < 16; kk++) {
            float4 aa0 = *(const float4*)&As[kk][n0];
            float4 aa1 = *(const float4*)&As[kk][n0 + 4];
            float4 ww0 = *(const float4*)&Ws[kk][m0];
            float4 ww1 = *(const float4*)&Ws[kk][m0 + 4];
            float am[8] = {aa0.x, aa0.y, aa0.z, aa0.w, aa1.x, aa1.y, aa1.z, aa1.w};
            float wm[8] = {ww0.x, ww0.y, ww0.z, ww0.w, ww1.x, ww1.y, ww1.z, ww1.w};
            #pragma unroll
            for (int i = 0; i < 8; i++)
                #pragma unroll
                for (int j = 0; j < 8; j++)
                    acc[i][j] = fmaf(wm[i], am[j], acc[i][j]);
        }
        __syncthreads();
    }

    float coef = 0.f;
    if (EPI == 1) coef = __ldg(coefp);
    #pragma unroll
    for (int i = 0; i < 8; i++) {
        int o = oBase + m0 + i;
        float bv = __ldg(bias + o);
        size_t row = (size_t)o * HW + p0 + n0;
        #pragma unroll
        for (int jv = 0; jv < 2; jv++) {
            float4 r;
            r.x = acc[i][jv*4+0] + bv;
            r.y = acc[i][jv*4+1] + bv;
            r.z = acc[i][jv*4+2] + bv;
            r.w = acc[i][jv*4+3] + bv;
            if (EPI == 1) {
                float4 res = *(const float4*)(Rb + row + jv*4);
                r.x = fmaf(coef, r.x, res.x);
                r.y = fmaf(coef, r.y, res.y);
                r.z = fmaf(coef, r.z, res.z);
                r.w = fmaf(coef, r.w, res.w);
            }
            *(float4*)(out + row + jv*4) = r;
        }
    }
}

// ---------------- depthwise 3x3 conv + bias + gated GELU ----------------
// g[i][p] = (dw3x3(y1,ch=i)+b[i]) * gelu(dw3x3(y1,ch=i+256)+b[i+256]),  i in [0,256)
__global__ __launch_bounds__(256)
void dwgate_kernel(const float* __restrict__ y1, const float* __restrict__ dww,
                   const float* __restrict__ dwb, float* __restrict__ g)
{
    int tile = blockIdx.x;            // 144 spatial tiles of 16x16
    int ci   = blockIdx.y;            // 0..255 channel pair
    int b    = blockIdx.z;
    int ty0 = (tile / (WW/16)) * 16;
    int tx0 = (tile % (WW/16)) * 16;
    __shared__ float su[18*18], sv[18*18];
    const float* ub = y1 + ((size_t)b*512 + ci)       * HW;
    const float* vb = y1 + ((size_t)b*512 + ci + 256) * HW;
    for (int i = threadIdx.x; i < 18*18; i += 256) {
        int ly = i / 18 - 1 + ty0, lx = i % 18 - 1 + tx0;
        bool in = (ly >= 0 && ly < HH && lx >= 0 && lx < WW);
        su[i] = in ? ub[ly*WW + lx] : 0.f;
        sv[i] = in ? vb[ly*WW + lx] : 0.f;
    }
    __syncthreads();
    int ly = threadIdx.x >> 4, lx = threadIdx.x & 15;
    float u = __ldg(dwb + ci), v = __ldg(dwb + ci + 256);
    #pragma unroll
    for (int dy = 0; dy < 3; ++dy)
        #pragma unroll
        for (int dx = 0; dx < 3; ++dx) {
            float wu = __ldg(dww + ci*9 + dy*3 + dx);
            float wv = __ldg(dww + (ci+256)*9 + dy*3 + dx);
            u = fmaf(wu, su[(ly+dy)*18 + lx+dx], u);
            v = fmaf(wv, sv[(ly+dy)*18 + lx+dx], v);
        }
    g[((size_t)b*256 + ci) * HW + (ty0+ly)*WW + tx0+lx] = u * gelu_f(v);
}

// ---------------- shifted-window attention (one block per 8x8 window) ----------------
__global__ __launch_bounds__(256)
void attn_kernel(const float* __restrict__ qkv, const float* __restrict__ rpe,
                 float* __restrict__ aout)
{
    __shared__ float q[64*33], k[64*33], v[64*33];
    __shared__ float S[64*65];
    __shared__ int pixmap[64];
    __shared__ int region[64];
    int tid = threadIdx.x;
    int b = blockIdx.y;
    int wy = blockIdx.x / 24, wx = blockIdx.x % 24;
    if (tid < 64) {
        int ti = tid >> 3, tj = tid & 7;
        int yr = wy*8 + ti, xr = wx*8 + tj;                 // rolled coords
        pixmap[tid] = ((yr + 4) % HH) * WW + ((xr + 4) % WW); // original pixel
        int rh = yr < HH-8 ? 0 : (yr < HH-4 ? 1 : 2);
        int rw = xr < WW-8 ? 0 : (xr < WW-4 ? 1 : 2);
        region[tid] = rh*3 + rw;
    }
    __syncthreads();
    const float* qb = qkv + (size_t)b * 384 * HW;
    for (int head = 0; head < 4; head++) {
        int ch = head * 32;
        for (int e = tid; e < 2048; e += 256) {
            int t = e & 63, d = e >> 6;
            int pix = pixmap[t];
            q[t*33+d] = qb[(size_t)(ch + d)       * HW + pix];
            k[t*33+d] = qb[(size_t)(128 + ch + d) * HW + pix];
            v[t*33+d] = qb[(size_t)(256 + ch + d) * HW + pix];
        }
        __syncthreads();
        {
            int t = tid >> 2;
            int regt = region[t];
            int ti = t >> 3, tj = t & 7;
            #pragma unroll 4
            for (int jj = 0; jj < 16; jj++) {
                int t2 = (tid & 3) + jj * 4;
                float acc = 0.f;
                #pragma unroll
                for (int d = 0; d < 32; d++) acc = fmaf(q[t*33+d], k[t2*33+d], acc);
                acc *= 0.17677669529663687f;                     // 1/sqrt(32)
                int dti = ti - (t2 >> 3) + 7;
                int dtj = tj - (t2 & 7) + 7;
                acc += __ldg(rpe + (dti*15 + dtj)*4 + head);
                if (region[t2] != regt) acc = -1e30f;
                S[t*65 + t2] = acc;
            }
        }
        __syncthreads();
        if (tid < 64) {
            float m = -1e30f;
            for (int j = 0; j < 64; j++) m = fmaxf(m, S[tid*65 + j]);
            float ssum = 0.f;
            for (int j = 0; j < 64; j++) { float e = __expf(S[tid*65 + j] - m); S[tid*65 + j] = e; ssum += e; }
            float inv = 1.f / ssum;
            for (int j = 0; j < 64; j++) S[tid*65 + j] *= inv;
        }
        __syncthreads();
        for (int e = tid; e < 2048; e += 256) {
            int t = e & 63, d = e >> 6;
            float acc = 0.f;
            #pragma unroll 8
            for (int t2 = 0; t2 < 64; t2++) acc = fmaf(S[t*65 + t2], v[t2*33 + d], acc);
            aout[(size_t)b*128*HW + (size_t)(ch + d)*HW + pixmap[t]] = acc;
        }
        __syncthreads();
    }
}

// ---------------- launch ----------------
extern "C" void kernel_launch(void* const* d_in, const int* in_sizes, int n_in,
                              void* d_out, int out_size)
{
    const float* x     = (const float*)d_in[0];
    const float* cg_s  = (const float*)d_in[1];
    const float* cg_b  = (const float*)d_in[2];
    const float* pw1_w = (const float*)d_in[3];
    const float* pw1_b = (const float*)d_in[4];
    const float* dw_w  = (const float*)d_in[5];
    const float* dw_b  = (const float*)d_in[6];
    const float* pw2_w = (const float*)d_in[7];
    const float* pw2_b = (const float*)d_in[8];
    const float* beta  = (const float*)d_in[9];
    const float* at_s  = (const float*)d_in[10];
    const float* at_b  = (const float*)d_in[11];
    const float* qkv_w = (const float*)d_in[12];
    const float* qkv_b = (const float*)d_in[13];
    const float* rpe   = (const float*)d_in[14];
    const float* proj_w= (const float*)d_in[15];
    const float* proj_b= (const float*)d_in[16];
    const float* alpha = (const float*)d_in[17];
    const float* ff_s  = (const float*)d_in[18];
    const float* ff_b  = (const float*)d_in[19];
    const float* fc1_w = (const float*)d_in[20];
    const float* fc1_b = (const float*)d_in[21];
    const float* fc2_w = (const float*)d_in[22];
    const float* fc2_b = (const float*)d_in[23];
    const float* gamma = (const float*)d_in[24];
    float* out = (float*)d_out;

    float *buf512, *qkvb, *gateb, *x1b, *invrb;
    cudaGetSymbolAddress((void**)&buf512, g_buf512);
    cudaGetSymbolAddress((void**)&qkvb,   g_qkv);
    cudaGetSymbolAddress((void**)&gateb,  g_gate);
    cudaGetSymbolAddress((void**)&x1b,    g_x1);
    cudaGetSymbolAddress((void**)&invrb,  g_invr);
    float* attnb = gateb;   // reuse: gate buffer is dead by attention time

    const long sC = (long)128 * HW, s256 = (long)256 * HW, s384 = (long)384 * HW, s512 = (long)512 * HW;
    dim3 blk(256);

    // ---- stage A: conv gated block ----
    invrms_kernel<<<(BATCH*HW)/256, blk>>>(x, invrb);
    gemm128<1,0><<<dim3(288,4,BATCH), blk>>>(pw1_w, x, pw1_b, cg_s, cg_b, invrb,
                                             nullptr, nullptr, buf512, 128, sC, s512);
    dwgate_kernel<<<dim3(144,256,BATCH), blk>>>(buf512, dw_w, dw_b, gateb);
    gemm128<0,1><<<dim3(288,1,BATCH), blk>>>(pw2_w, gateb, pw2_b, nullptr, nullptr, nullptr,
                                             x, beta, x1b, 256, s256, sC);
    // ---- stage B: window attention ----
    invrms_kernel<<<(BATCH*HW)/256, blk>>>(x1b, invrb);
    gemm128<1,0><<<dim3(288,3,BATCH), blk>>>(qkv_w, x1b, qkv_b, at_s, at_b, invrb,
                                             nullptr, nullptr, qkvb, 128, sC, s384);
    attn_kernel<<<dim3(576,BATCH), blk>>>(qkvb, rpe, attnb);
    gemm128<0,1><<<dim3(288,1,BATCH), blk>>>(proj_w, attnb, proj_b, nullptr, nullptr, nullptr,
                                             x1b, alpha, out, 128, sC, sC);
    // ---- stage C: gated FFN ----
    invrms_kernel<<<(BATCH*HW)/256, blk>>>(out, invrb);
    gemm128<1,0><<<dim3(288,4,BATCH), blk>>>(fc1_w, out, fc1_b, ff_s, ff_b, invrb,
                                             nullptr, nullptr, buf512, 128, sC, s512);
    gemm128<2,1><<<dim3(288,1,BATCH), blk>>>(fc2_w, buf512, fc2_b, nullptr, nullptr, nullptr,
                                             out, gamma, out, 256, s512, sC);
}

// round 2
// speedup vs baseline: 1.4942x; 1.4942x over previous
#include <cuda_runtime.h>
#include <math.h>

#define HH 192
#define WW 192
#define HW (HH*WW)       // 36864
#define CB 128
#define BATCH 2

// ---------------- scratch (device globals; no runtime allocation) ----------------
__device__ float g_buf512[(size_t)BATCH*512*HW];  // y1 (stage A) / z1 (stage C)
__device__ float g_qkv  [(size_t)BATCH*384*HW];   // qkv
__device__ float g_gate [(size_t)BATCH*256*HW];   // gated act (stage A) / attn out (reuse)
__device__ float g_x1   [(size_t)BATCH*128*HW];   // x after conv block
__device__ float g_invr [(size_t)BATCH*HW];       // per-pixel 1/rms

__device__ __forceinline__ float gelu_f(float x) {
    return 0.5f * x * (1.0f + erff(x * 0.70710678118654752f));
}

__device__ __forceinline__ unsigned to_tf32(float f) {
    unsigned u;
    asm("cvt.rna.tf32.f32 %0, %1;" : "=r"(u) : "f"(f));
    return u;
}

// ---------------- per-pixel inverse RMS over 128 channels ----------------
__global__ void invrms_kernel(const float* __restrict__ x, float* __restrict__ invr) {
    int idx = blockIdx.x * blockDim.x + threadIdx.x;   // 0..B*HW-1
    int b = idx / HW, p = idx - b * HW;
    const float* xp = x + (size_t)b * CB * HW + p;
    float acc = 0.f;
    #pragma unroll 8
    for (int c = 0; c < CB; ++c) { float v = xp[(size_t)c * HW]; acc = fmaf(v, v, acc); }
    invr[idx] = rsqrtf(acc * (1.0f / CB) + 1e-6f);
}

// ---------------- tf32 tensor-core fused GEMM ----------------
// out[o][p] = epi( sum_k W[o][k] * Aval(k,p) )
// AMODE 0: Aval = A[k][p]
// AMODE 1: Aval = s[k]*A[k][p]*invr[p] + rb[k]          (rmsnorm fused)
// AMODE 2: Aval = A[k][p] * gelu(A[k+256][p])           (gated-GELU fused, K=256)
// EPI 0:   out = acc + bias[o]
// EPI 1:   out = R[o][p] + coef*(acc + bias[o])
// Tile: BM=128 (o), BN=128 (p), BK=16. 256 thr = 8 warps (4 in M x 2 in N),
// warp tile 32x64 via m16n8k8 tf32 mma (2 M-tiles x 8 N-tiles, 2 k-steps).
template<int AMODE, int EPI>
__global__ __launch_bounds__(256)
void gemm128(const float* __restrict__ W,
             const float* __restrict__ A,
             const float* __restrict__ bias,
             const float* __restrict__ s,
             const float* __restrict__ rb,
             const float* __restrict__ invr,
             const float* __restrict__ R,
             const float* __restrict__ coefp,
             float* __restrict__ out,
             int K, long strideA, long strideO)
{
    __shared__ unsigned Ws[16][136];   // [k][m], pad 136 -> bank = (8k+m)%32
    __shared__ unsigned As[16][136];   // [k][n]

    int b = blockIdx.z;
    int p0 = blockIdx.x * 128;
    int oBase = blockIdx.y * 128;
    A   += (size_t)b * strideA;
    out += (size_t)b * strideO;
    const float* Rb   = (EPI == 1) ? (R + (size_t)b * 128 * HW) : nullptr;
    const float* invb = (AMODE == 1) ? (invr + (size_t)b * HW) : nullptr;

    int tid = threadIdx.x;
    int lane = tid & 31;
    int warp = tid >> 5;
    int wm0 = (warp & 3) * 32;     // warp M offset
    int wn0 = (warp >> 2) * 64;    // warp N offset
    int lk = lane & 3;             // k within 4
    int lr = lane >> 2;            // 0..7

    // smem staging indices
    int wo = tid >> 1;             // 0..127 (W row)
    int wc = (tid & 1) * 8;        // 0/8    (W k chunk)
    int ak = tid >> 4;             // 0..15  (A k row)
    int ap = (tid & 15) * 8;       // 0..120 (A pixel chunk)

    float acc[2][8][4];
    #pragma unroll
    for (int mt = 0; mt < 2; mt++)
        #pragma unroll
        for (int nt = 0; nt < 8; nt++)
            #pragma unroll
            for (int r = 0; r < 4; r++) acc[mt][nt][r] = 0.f;

    for (int k0 = 0; k0 < K; k0 += 16) {
        // W tile -> Ws[k][m] (tf32)
        {
            const float* wp = W + (size_t)(oBase + wo) * K + (k0 + wc);
            float4 w0 = *(const float4*)wp;
            float4 w1 = *(const float4*)(wp + 4);
            Ws[wc+0][wo] = to_tf32(w0.x); Ws[wc+1][wo] = to_tf32(w0.y);
            Ws[wc+2][wo] = to_tf32(w0.z); Ws[wc+3][wo] = to_tf32(w0.w);
            Ws[wc+4][wo] = to_tf32(w1.x); Ws[wc+5][wo] = to_tf32(w1.y);
            Ws[wc+6][wo] = to_tf32(w1.z); Ws[wc+7][wo] = to_tf32(w1.w);
        }
        // A tile -> As[k][n] (fused transform, tf32)
        {
            const float* ag = A + (size_t)(k0 + ak) * HW + (p0 + ap);
            float4 a0 = *(const float4*)ag;
            float4 a1 = *(const float4*)(ag + 4);
            if (AMODE == 1) {
                float sc = __ldg(s + k0 + ak), bb = __ldg(rb + k0 + ak);
                float4 i0 = *(const float4*)(invb + p0 + ap);
                float4 i1 = *(const float4*)(invb + p0 + ap + 4);
                a0.x = fmaf(sc*a0.x, i0.x, bb); a0.y = fmaf(sc*a0.y, i0.y, bb);
                a0.z = fmaf(sc*a0.z, i0.z, bb); a0.w = fmaf(sc*a0.w, i0.w, bb);
                a1.x = fmaf(sc*a1.x, i1.x, bb); a1.y = fmaf(sc*a1.y, i1.y, bb);
                a1.z = fmaf(sc*a1.z, i1.z, bb); a1.w = fmaf(sc*a1.w, i1.w, bb);
            } else if (AMODE == 2) {
                const float* vg = ag + (size_t)256 * HW;
                float4 v0 = *(const float4*)vg;
                float4 v1 = *(const float4*)(vg + 4);
                a0.x *= gelu_f(v0.x); a0.y *= gelu_f(v0.y);
                a0.z *= gelu_f(v0.z); a0.w *= gelu_f(v0.w);
                a1.x *= gelu_f(v1.x); a1.y *= gelu_f(v1.y);
                a1.z *= gelu_f(v1.z); a1.w *= gelu_f(v1.w);
            }
            uint4 u0, u1;
            u0.x = to_tf32(a0.x); u0.y = to_tf32(a0.y); u0.z = to_tf32(a0.z); u0.w = to_tf32(a0.w);
            u1.x = to_tf32(a1.x); u1.y = to_tf32(a1.y); u1.z = to_tf32(a1.z); u1.w = to_tf32(a1.w);
            *(uint4*)&As[ak][ap]     = u0;
            *(uint4*)&As[ak][ap + 4] = u1;
        }
        __syncthreads();

        #pragma unroll
        for (int ks = 0; ks < 2; ks++) {
            int kb = ks * 8;
            unsigned af[2][4], bf[8][2];
            #pragma unroll
            for (int mt = 0; mt < 2; mt++) {
                int m = wm0 + mt * 16 + lr;
                af[mt][0] = Ws[kb + lk    ][m];
                af[mt][1] = Ws[kb + lk    ][m + 8];
                af[mt][2] = Ws[kb + lk + 4][m];
                af[mt][3] = Ws[kb + lk + 4][m + 8];
            }
            #pragma unroll
            for (int nt = 0; nt < 8; nt++) {
                int n = wn0 + nt * 8 + lr;
                bf[nt][0] = As[kb + lk    ][n];
                bf[nt][1] = As[kb + lk + 4][n];
            }
            #pragma unroll
            for (int mt = 0; mt < 2; mt++)
                #pragma unroll
                for (int nt = 0; nt < 8; nt++) {
                    asm volatile(
                        "mma.sync.aligned.m16n8k8.row.col.f32.tf32.tf32.f32 "
                        "{%0,%1,%2,%3}, {%4,%5,%6,%7}, {%8,%9}, {%0,%1,%2,%3};"
                        : "+f"(acc[mt][nt][0]), "+f"(acc[mt][nt][1]),
                          "+f"(acc[mt][nt][2]), "+f"(acc[mt][nt][3])
                        : "r"(af[mt][0]), "r"(af[mt][1]), "r"(af[mt][2]), "r"(af[mt][3]),
                          "r"(bf[nt][0]), "r"(bf[nt][1]));
                }
        }
        __syncthreads();
    }

    // Epilogue: c0/c1 -> (row lr, cols c2,c2+1), c2/c3 -> (row lr+8)
    float coef = 0.f;
    if (EPI == 1) coef = __ldg(coefp);
    int c2 = (lane & 3) * 2;
    #pragma unroll
    for (int mt = 0; mt < 2; mt++) {
        #pragma unroll
        for (int half = 0; half < 2; half++) {
            int o = oBase + wm0 + mt * 16 + lr + half * 8;
            float bv = __ldg(bias + o);
            size_t rowoff = (size_t)o * HW + p0 + wn0 + c2;
            #pragma unroll
            for (int nt = 0; nt < 8; nt++) {
                float v0 = acc[mt][nt][half*2+0] + bv;
                float v1 = acc[mt][nt][half*2+1] + bv;
                size_t off = rowoff + nt * 8;
                if (EPI == 1) {
                    float2 res = *(const float2*)(Rb + off);
                    v0 = fmaf(coef, v0, res.x);
                    v1 = fmaf(coef, v1, res.y);
                }
                float2 r2; r2.x = v0; r2.y = v1;
                *(float2*)(out + off) = r2;
            }
        }
    }
}

// ---------------- depthwise 3x3 conv + bias + gated GELU ----------------
__global__ __launch_bounds__(256)
void dwgate_kernel(const float* __restrict__ y1, const float* __restrict__ dww,
                   const float* __restrict__ dwb, float* __restrict__ g)
{
    int tile = blockIdx.x;            // 144 spatial tiles of 16x16
    int ci   = blockIdx.y;            // 0..255 channel pair
    int b    = blockIdx.z;
    int ty0 = (tile / (WW/16)) * 16;
    int tx0 = (tile % (WW/16)) * 16;
    __shared__ float su[18*18], sv[18*18];
    const float* ub = y1 + ((size_t)b*512 + ci)       * HW;
    const float* vb = y1 + ((size_t)b*512 + ci + 256) * HW;
    for (int i = threadIdx.x; i < 18*18; i += 256) {
        int ly = i / 18 - 1 + ty0, lx = i % 18 - 1 + tx0;
        bool in = (ly >= 0 && ly < HH && lx >= 0 && lx < WW);
        su[i] = in ? ub[ly*WW + lx] : 0.f;
        sv[i] = in ? vb[ly*WW + lx] : 0.f;
    }
    __syncthreads();
    int ly = threadIdx.x >> 4, lx = threadIdx.x & 15;
    float u = __ldg(dwb + ci), v = __ldg(dwb + ci + 256);
    #pragma unroll
    for (int dy = 0; dy < 3; ++dy)
        #pragma unroll
        for (int dx = 0; dx < 3; ++dx) {
            float wu = __ldg(dww + ci*9 + dy*3 + dx);
            float wv = __ldg(dww + (ci+256)*9 + dy*3 + dx);
            u = fmaf(wu, su[(ly+dy)*18 + lx+dx], u);
            v = fmaf(wv, sv[(ly+dy)*18 + lx+dx], v);
        }
    g[((size_t)b*256 + ci) * HW + (ty0+ly)*WW + tx0+lx] = u * gelu_f(v);
}

// ---------------- shifted-window attention (one block per 8x8 window) ----------------
__global__ __launch_bounds__(256)
void attn_kernel(const float* __restrict__ qkv, const float* __restrict__ rpe,
                 float* __restrict__ aout)
{
    __shared__ float q[64*33], k[64*33], v[64*33];
    __shared__ float S[64*65];
    __shared__ int pixmap[64];
    __shared__ int region[64];
    int tid = threadIdx.x;
    int b = blockIdx.y;
    int wy = blockIdx.x / 24, wx = blockIdx.x % 24;
    if (tid < 64) {
        int ti = tid >> 3, tj = tid & 7;
        int yr = wy*8 + ti, xr = wx*8 + tj;                 // rolled coords
        pixmap[tid] = ((yr + 4) % HH) * WW + ((xr + 4) % WW); // original pixel
        int rh = yr < HH-8 ? 0 : (yr < HH-4 ? 1 : 2);
        int rw = xr < WW-8 ? 0 : (xr < WW-4 ? 1 : 2);
        region[tid] = rh*3 + rw;
    }
    __syncthreads();
    const float* qb = qkv + (size_t)b * 384 * HW;
    for (int head = 0; head < 4; head++) {
        int ch = head * 32;
        for (int e = tid; e < 2048; e += 256) {
            int t = e & 63, d = e >> 6;
            int pix = pixmap[t];
            q[t*33+d] = qb[(size_t)(ch + d)       * HW + pix];
            k[t*33+d] = qb[(size_t)(128 + ch + d) * HW + pix];
            v[t*33+d] = qb[(size_t)(256 + ch + d) * HW + pix];
        }
        __syncthreads();
        {
            int t = tid >> 2;
            int regt = region[t];
            int ti = t >> 3, tj = t & 7;
            #pragma unroll 4
            for (int jj = 0; jj < 16; jj++) {
                int t2 = (tid & 3) + jj * 4;
                float acc = 0.f;
                #pragma unroll
                for (int d = 0; d < 32; d++) acc = fmaf(q[t*33+d], k[t2*33+d], acc);
                acc *= 0.17677669529663687f;                     // 1/sqrt(32)
                int dti = ti - (t2 >> 3) + 7;
                int dtj = tj - (t2 & 7) + 7;
                acc += __ldg(rpe + (dti*15 + dtj)*4 + head);
                if (region[t2] != regt) acc = -1e30f;
                S[t*65 + t2] = acc;
            }
        }
        __syncthreads();
        if (tid < 64) {
            float m = -1e30f;
            for (int j = 0; j < 64; j++) m = fmaxf(m, S[tid*65 + j]);
            float ssum = 0.f;
            for (int j = 0; j < 64; j++) { float e = __expf(S[tid*65 + j] - m); S[tid*65 + j] = e; ssum += e; }
            float inv = 1.f / ssum;
            for (int j = 0; j < 64; j++) S[tid*65 + j] *= inv;
        }
        __syncthreads();
        for (int e = tid; e < 2048; e += 256) {
            int t = e & 63, d = e >> 6;
            float acc = 0.f;
            #pragma unroll 8
            for (int t2 = 0; t2 < 64; t2++) acc = fmaf(S[t*65 + t2], v[t2*33 + d], acc);
            aout[(size_t)b*128*HW + (size_t)(ch + d)*HW + pixmap[t]] = acc;
        }
        __syncthreads();
    }
}

// ---------------- launch ----------------
extern "C" void kernel_launch(void* const* d_in, const int* in_sizes, int n_in,
                              void* d_out, int out_size)
{
    const float* x     = (const float*)d_in[0];
    const float* cg_s  = (const float*)d_in[1];
    const float* cg_b  = (const float*)d_in[2];
    const float* pw1_w = (const float*)d_in[3];
    const float* pw1_b = (const float*)d_in[4];
    const float* dw_w  = (const float*)d_in[5];
    const float* dw_b  = (const float*)d_in[6];
    const float* pw2_w = (const float*)d_in[7];
    const float* pw2_b = (const float*)d_in[8];
    const float* beta  = (const float*)d_in[9];
    const float* at_s  = (const float*)d_in[10];
    const float* at_b  = (const float*)d_in[11];
    const float* qkv_w = (const float*)d_in[12];
    const float* qkv_b = (const float*)d_in[13];
    const float* rpe   = (const float*)d_in[14];
    const float* proj_w= (const float*)d_in[15];
    const float* proj_b= (const float*)d_in[16];
    const float* alpha = (const float*)d_in[17];
    const float* ff_s  = (const float*)d_in[18];
    const float* ff_b  = (const float*)d_in[19];
    const float* fc1_w = (const float*)d_in[20];
    const float* fc1_b = (const float*)d_in[21];
    const float* fc2_w = (const float*)d_in[22];
    const float* fc2_b = (const float*)d_in[23];
    const float* gamma = (const float*)d_in[24];
    float* out = (float*)d_out;

    float *buf512, *qkvb, *gateb, *x1b, *invrb;
    cudaGetSymbolAddress((void**)&buf512, g_buf512);
    cudaGetSymbolAddress((void**)&qkvb,   g_qkv);
    cudaGetSymbolAddress((void**)&gateb,  g_gate);
    cudaGetSymbolAddress((void**)&x1b,    g_x1);
    cudaGetSymbolAddress((void**)&invrb,  g_invr);
    float* attnb = gateb;   // reuse: gate buffer is dead by attention time

    const long sC = (long)128 * HW, s256 = (long)256 * HW, s384 = (long)384 * HW, s512 = (long)512 * HW;
    dim3 blk(256);

    // ---- stage A: conv gated block ----
    invrms_kernel<<<(BATCH*HW)/256, blk>>>(x, invrb);
    gemm128<1,0><<<dim3(288,4,BATCH), blk>>>(pw1_w, x, pw1_b, cg_s, cg_b, invrb,
                                             nullptr, nullptr, buf512, 128, sC, s512);
    dwgate_kernel<<<dim3(144,256,BATCH), blk>>>(buf512, dw_w, dw_b, gateb);
    gemm128<0,1><<<dim3(288,1,BATCH), blk>>>(pw2_w, gateb, pw2_b, nullptr, nullptr, nullptr,
                                             x, beta, x1b, 256, s256, sC);
    // ---- stage B: window attention ----
    invrms_kernel<<<(BATCH*HW)/256, blk>>>(x1b, invrb);
    gemm128<1,0><<<dim3(288,3,BATCH), blk>>>(qkv_w, x1b, qkv_b, at_s, at_b, invrb,
                                             nullptr, nullptr, qkvb, 128, sC, s384);
    attn_kernel<<<dim3(576,BATCH), blk>>>(qkvb, rpe, attnb);
    gemm128<0,1><<<dim3(288,1,BATCH), blk>>>(proj_w, attnb, proj_b, nullptr, nullptr, nullptr,
                                             x1b, alpha, out, 128, sC, sC);
    // ---- stage C: gated FFN ----
    invrms_kernel<<<(BATCH*HW)/256, blk>>>(out, invrb);
    gemm128<1,0><<<dim3(288,4,BATCH), blk>>>(fc1_w, out, fc1_b, ff_s, ff_b, invrb,
                                             nullptr, nullptr, buf512, 128, sC, s512);
    gemm128<2,1><<<dim3(288,1,BATCH), blk>>>(fc2_w, buf512, fc2_b, nullptr, nullptr, nullptr,
                                             out, gamma, out, 256, s512, sC);
}